// round 4
// baseline (speedup 1.0000x reference)
#include <cuda_runtime.h>

#define KCH    32
#define HW     64
#define TSTEPS 100
#define PLANE  4096
#define NCTA   128
#define NTHR   512
#define ROWS_L 60
#define RPITCH 65

// Double-buffered recurrent state X_t, and single-buffered feat scratch Y_t.
__device__ float g_state[2][2 * KCH * PLANE];
__device__ float g_feat[2 * KCH * PLANE];

// Synchronization. All counters monotonic across graph replays except the
// cnt fields, which a releaser returns to 0 each step. Base values are read
// before the initial full barrier; all arrivals happen after it.
__device__ unsigned g_bar_cnt, g_bar_gen;
__device__ unsigned g_xcnt[4], g_xgen[4];   // index = n*2 + half; X_t published
__device__ unsigned g_ycnt[4], g_ygen[4];   // index = n*2 + half; Y_t published
__device__ unsigned g_flags[NCTA];          // per-CTA X publication (partner halo)

__device__ __forceinline__ unsigned ld_acq(const unsigned* p) {
    unsigned v;
    asm volatile("ld.acquire.gpu.global.u32 %0, [%1];" : "=r"(v) : "l"(p) : "memory");
    return v;
}
__device__ __forceinline__ void st_rel(unsigned* p, unsigned v) {
    asm volatile("st.release.gpu.global.u32 [%0], %1;" :: "l"(p), "r"(v) : "memory");
}

__global__ void __launch_bounds__(NTHR, 1)
persist_kernel(const float* __restrict__ inbound,
               const float* __restrict__ Wf,
               const float* __restrict__ bf,
               const float* __restrict__ Ws,
               const float* __restrict__ bs,
               float* __restrict__ out)
{
    extern __shared__ float sm[];
    float* R   = sm;                           // [60][65] own-channel X_t halo rows
    float* H29 = R   + ROWS_L * RPITCH;        // [60][65] 29-wide horizontal sums
    float* H9  = H29 + ROWS_L * RPITCH;        // [60][65] 9-wide horizontal sums
    float* Xs  = H9  + ROWS_L * RPITCH;        // [32][64] slab staging (all ch, 1 row)
    __shared__ unsigned sb[4];

    const int b   = blockIdx.x;                // 0..127
    const int tid = threadIdx.x;

    // surround role
    const int n       = b >> 6;
    const int k       = (b & 63) >> 1;
    const int h       = b & 1;
    const int r0      = h << 5;
    const int partner = b ^ 1;
    // slab role (feat): one row, all channels
    const int row_s   = b & 63;
    const int shalf   = row_s >> 5;

    if (tid == 0) {
        sb[0] = ld_acq(&g_xgen[n * 2 + shalf]);   // wait group for slab reads
        sb[1] = ld_acq(&g_ygen[n * 2 + h]);       // wait group for V reads
        sb[2] = ld_acq(&g_flags[b]);              // == partner's base
        sb[3] = ld_acq(&g_bar_gen);
    }

    // surround constants
    const float bs_k = bs[k];
    const float inh  = Ws[k * 841];
    const float emin = Ws[k * 841 + 420] - inh;

    // feat-role mapping: warp lanes span all 32 output channels at one pixel
    const int o    = tid & 31;                 // output channel
    const int wq_f = (tid >> 5) << 2;          // 4-pixel group
    float wfr[KCH];
    #pragma unroll
    for (int i = 0; i < KCH; i++) wfr[i] = Wf[o * KCH + i];
    const size_t slab_off = (size_t)row_s * HW;
    const float4 inb4 = *(const float4*)(inbound + (size_t)(n * KCH + o) * PLANE
                                         + slab_off + wq_f);
    const float bf_o  = bf[o];
    float4 base4 = make_float4(0.5f * inb4.x + bf_o, 0.5f * inb4.y + bf_o,
                               0.5f * inb4.z + bf_o, 0.5f * inb4.w + bf_o);

    // H-phase mapping
    const int j_h = tid >> 3;
    const int s_h = (tid & 7) << 3;
    // V-phase mapping: 512 threads, 4-row segments
    const int w_v = tid & 63;
    const int rb  = (tid >> 6) << 2;

    const size_t plane_off = (size_t)(n * KCH + k) * PLANE;

    // zero R/H29/H9 (X_0 = 0 path)
    for (int i = tid; i < 3 * ROWS_L * RPITCH; i += NTHR) sm[i] = 0.f;
    __syncthreads();
    const unsigned xbase = sb[0], ybase = sb[1], fbase = sb[2], gen0 = sb[3];

    // ---- initial full grid barrier: separates base reads from all arrivals ----
    if (tid == 0) {
        __threadfence();
        if (atomicAdd(&g_bar_cnt, 1u) == NCTA - 1) {
            g_bar_cnt = 0;
            st_rel(&g_bar_gen, gen0 + 1);
        } else {
            while ((int)(ld_acq(&g_bar_gen) - (gen0 + 1)) < 0) { }
        }
    }
    __syncthreads();

    for (int t = 0; t < TSTEPS; t++) {
        // ================= Region A: halo + slab load + feat + H =================
        if (t > 0) {
            if (tid == 0) {
                const unsigned xt = xbase + (unsigned)t;
                while ((int)(ld_acq(&g_xgen[n * 2 + shalf]) - xt) < 0) { }
                const unsigned ft = fbase + (unsigned)t;
                while ((int)(ld_acq(&g_flags[partner]) - ft) < 0) { }
            }
            __syncthreads();

            const float* src = g_state[t & 1];
            // own-channel halo rows -> R
            #pragma unroll
            for (int it = 0; it < 2; it++) {
                int idx = tid + it * NTHR;
                if (idx < ROWS_L * 16) {
                    int j  = idx >> 4;
                    int wq = (idx & 15) << 2;
                    int gr = r0 - 14 + j;
                    float4 v = make_float4(0.f, 0.f, 0.f, 0.f);
                    if (gr >= 0 && gr < HW)
                        v = *(const float4*)(src + plane_off + gr * HW + wq);
                    float* rp = &R[j * RPITCH + wq];
                    rp[0] = v.x; rp[1] = v.y; rp[2] = v.z; rp[3] = v.w;
                }
            }
            // slab: all 32 channels of row_s -> Xs (coalesced, one float4/thread)
            {
                const int i_l  = tid >> 4;
                const int wq_l = (tid & 15) << 2;
                *(float4*)&Xs[i_l * HW + wq_l] =
                    *(const float4*)(src + (size_t)(n * KCH + i_l) * PLANE
                                     + slab_off + wq_l);
            }
            __syncthreads();
        }

        // feat: Y = base + Wf @ X  (broadcast LDS: whole warp reads same pixel)
        {
            float4 acc = base4;
            if (t > 0) {
                #pragma unroll
                for (int i = 0; i < KCH; i++) {
                    const float4 x = *(const float4*)&Xs[i * HW + wq_f];
                    acc.x += wfr[i] * x.x; acc.y += wfr[i] * x.y;
                    acc.z += wfr[i] * x.z; acc.w += wfr[i] * x.w;
                }
            }
            *(float4*)(g_feat + (size_t)(n * KCH + o) * PLANE + slab_off + wq_f) = acc;
        }
        __syncthreads();
        if (tid == 0) {                        // publish Y slab
            __threadfence();
            const int g = n * 2 + shalf;
            if (atomicAdd(&g_ycnt[g], 1u) == 31u) {
                unsigned cur = ld_acq(&g_ygen[g]);
                g_ycnt[g] = 0;
                st_rel(&g_ygen[g], cur + 1);
            }
        }

        // H phase: horizontal box sums (register sliding windows)
        if (t > 0 && j_h < ROWS_L) {
            float v[36];
            const float* row = &R[j_h * RPITCH];
            #pragma unroll
            for (int d = 0; d < 36; d++) {
                int w = s_h - 14 + d;
                v[d] = (w >= 0 && w < HW) ? row[w] : 0.f;
            }
            float sa = 0.f, sc = 0.f;
            #pragma unroll
            for (int d = 0; d < 14; d++) { sa += v[d]; sc += v[d + 14]; }
            float s29 = sa + sc + v[28];
            H29[j_h * RPITCH + s_h] = s29;
            #pragma unroll
            for (int p = 1; p < 8; p++) {
                s29 += v[p + 28] - v[p - 1];
                H29[j_h * RPITCH + s_h + p] = s29;
            }
            float s9 = 0.f;
            #pragma unroll
            for (int d = 10; d < 19; d++) s9 += v[d];
            H9[j_h * RPITCH + s_h] = s9;
            #pragma unroll
            for (int p = 1; p < 8; p++) {
                s9 += v[p + 18] - v[p + 9];
                H9[j_h * RPITCH + s_h + p] = s9;
            }
        }

        // ================= Region B: V + combine + emit =================
        if (tid == 0) {
            const unsigned yt = ybase + (unsigned)t + 1u;
            while ((int)(ld_acq(&g_ygen[n * 2 + h]) - yt) < 0) { }
        }
        __syncthreads();

        {
            const float* Yp = g_feat + plane_off;
            float yv[4];
            #pragma unroll
            for (int r = 0; r < 4; r++) yv[r] = Yp[(size_t)(r0 + rb + r) * HW + w_v];

            float b29a = 0.f, b29b = 0.f, b9 = 0.f;
            #pragma unroll
            for (int d = 0; d < 14; d++) {
                b29a += H29[(rb + d) * RPITCH + w_v];
                b29b += H29[(rb + 14 + d) * RPITCH + w_v];
            }
            float b29 = b29a + b29b + H29[(rb + 28) * RPITCH + w_v];
            #pragma unroll
            for (int d = 0; d < 9; d++) b9 += H9[(rb + 10 + d) * RPITCH + w_v];

            float* dst = g_state[(t + 1) & 1];
            const size_t outb = ((size_t)(n * TSTEPS + t) * KCH + k) * PLANE;
            #pragma unroll
            for (int r = 0; r < 4; r++) {
                const int rr = rb + r;
                const int j  = rr + 14;
                if (r > 0) {
                    b29 += H29[(rr + 28) * RPITCH + w_v] - H29[(rr - 1) * RPITCH + w_v];
                    b9  += H9 [(j + 4)  * RPITCH + w_v] - H9 [(j - 5)  * RPITCH + w_v];
                }
                const float sp = inh * b29 + emin * b9 + bs_k;
                const float xo = R[j * RPITCH + w_v];
                const float xn = 0.8f * xo + 0.2f * fmaxf(yv[r] + sp, 0.f);
                dst[plane_off + (size_t)(r0 + rr) * HW + w_v] = xn;
                out[outb     + (size_t)(r0 + rr) * HW + w_v] = xn;
            }
        }

        if (t == TSTEPS - 1) break;

        __syncthreads();                       // all V reads done, X_{t+1} stored
        if (tid == 0) {                        // publish X_{t+1}
            __threadfence();
            st_rel(&g_flags[b], fbase + (unsigned)t + 1u);
            const int g = n * 2 + h;
            if (atomicAdd(&g_xcnt[g], 1u) == 31u) {
                unsigned cur = ld_acq(&g_xgen[g]);
                g_xcnt[g] = 0;
                st_rel(&g_xgen[g], cur + 1);
            }
        }
    }
}

extern "C" void kernel_launch(void* const* d_in, const int* in_sizes, int n_in,
                              void* d_out, int out_size)
{
    const float* inbound = (const float*)d_in[0];
    const float* Wf      = (const float*)d_in[1];
    const float* bf      = (const float*)d_in[2];
    const float* Ws      = (const float*)d_in[3];
    const float* bs      = (const float*)d_in[4];
    float* out = (float*)d_out;

    const int smem_bytes = (3 * ROWS_L * RPITCH + KCH * HW) * sizeof(float);
    static bool attr_set = false;
    if (!attr_set) {
        cudaFuncSetAttribute(persist_kernel,
                             cudaFuncAttributeMaxDynamicSharedMemorySize, smem_bytes);
        attr_set = true;
    }
    persist_kernel<<<NCTA, NTHR, smem_bytes>>>(inbound, Wf, bf, Ws, bs, out);
}

// round 5
// speedup vs baseline: 1.1134x; 1.1134x over previous
#include <cuda_runtime.h>

#define KCH    32
#define HW     64
#define TSTEPS 100
#define PLANE  4096
#define NCTA   128
#define NTHR   512
#define ROWS_L 60
#define RP     65

// Double-buffered recurrent state X_t. Step t reads g_state[t&1], writes g_state[(t+1)&1].
__device__ float g_state[2][2 * KCH * PLANE];

// Full-grid barrier. gen is monotonic across graph replays (relative compares only);
// cnt is reset to 0 by each releaser. Each CTA reads its base gen before its first
// arrive, and the release needs all arrivals, so base reads always precede release.
__device__ unsigned g_bar_cnt, g_bar_gen;

__device__ __forceinline__ unsigned ld_acq(const unsigned* p) {
    unsigned v;
    asm volatile("ld.acquire.gpu.global.u32 %0, [%1];" : "=r"(v) : "l"(p) : "memory");
    return v;
}
__device__ __forceinline__ void st_rel(unsigned* p, unsigned v) {
    asm volatile("st.release.gpu.global.u32 [%0], %1;" :: "l"(p), "r"(v) : "memory");
}

__global__ void __launch_bounds__(NTHR, 1)
persist_kernel(const float* __restrict__ inbound,
               const float* __restrict__ Wf,
               const float* __restrict__ bf,
               const float* __restrict__ Ws,
               const float* __restrict__ bs,
               float* __restrict__ out)
{
    extern __shared__ float sm[];
    float* Rb[2];
    Rb[0]      = sm;                          // [60][65] X halo rows, even steps
    Rb[1]      = Rb[0] + ROWS_L * RP;         // [60][65] X halo rows, odd steps
    float* H29 = Rb[1] + ROWS_L * RP;         // [60][65] 29-wide horizontal sums
    float* H9  = H29   + ROWS_L * RP;         // [60][65] 9-wide horizontal sums
    float* S   = H9    + ROWS_L * RP;         // [32][64] feat + 0.5*inb + bf
    float* WfS = S + 32 * HW;                 // Wf row for this channel
    __shared__ unsigned sgen;

    const int b   = blockIdx.x;               // 0..127
    const int tid = threadIdx.x;
    const int n   = b >> 6;
    const int k   = (b & 63) >> 1;
    const int h   = b & 1;
    const int r0  = h << 5;
    const size_t plane_off = (size_t)(n * KCH + k) * PLANE;

    if (tid < KCH) WfS[tid] = Wf[k * KCH + tid];
    if (tid == 0)  sgen = ld_acq(&g_bar_gen);

    const float bf_k = bf[k];
    const float bs_k = bs[k];
    const float inh  = Ws[k * 841];                 // uniform inhibition value
    const float emin = Ws[k * 841 + 420] - inh;     // center excitation minus inh

    // zero both R buffers (static zero edge rows + X_0 = 0 interior)
    for (int i = tid; i < 2 * ROWS_L * RP; i += NTHR) sm[i] = 0.f;

    // ---- feat-group mapping (warps 0-7): row rr_f, 8 contiguous pixels ----
    const int rr_f = tid >> 3;                // 0..31 for tid<256
    const int w0_f = (tid & 7) << 3;
    float base[8];
    if (tid < 256) {
        const float4 i0 = *(const float4*)(inbound + plane_off + (r0 + rr_f) * HW + w0_f);
        const float4 i1 = *(const float4*)(inbound + plane_off + (r0 + rr_f) * HW + w0_f + 4);
        base[0] = 0.5f * i0.x + bf_k; base[1] = 0.5f * i0.y + bf_k;
        base[2] = 0.5f * i0.z + bf_k; base[3] = 0.5f * i0.w + bf_k;
        base[4] = 0.5f * i1.x + bf_k; base[5] = 0.5f * i1.y + bf_k;
        base[6] = 0.5f * i1.z + bf_k; base[7] = 0.5f * i1.w + bf_k;
    }
    const int tid2 = tid - 256;               // H-group local id (0..255)

    // ---- V mapping: 512 threads, (column, 4-row segment) ----
    const int w_v = tid & 63;
    const int rb  = (tid >> 6) << 2;

    // partner halo rows: h=0 needs global rows 32..45 into j=46..59;
    //                    h=1 needs global rows 18..31 into j=0..13
    const int pj0 = h ? 0 : 46;
    const int pg0 = h ? 18 : 32;

    __syncthreads();
    const unsigned gen0 = sgen;

    for (int t = 0; t < TSTEPS; t++) {
        float* R_cur = Rb[t & 1];
        float* R_nxt = Rb[(t + 1) & 1];

        if (tid < 256) {
            // ======== feat: S = base + Wf @ X_t (all channels, global) ========
            float a[8];
            #pragma unroll
            for (int p = 0; p < 8; p++) a[p] = base[p];
            if (t > 0) {
                const float4* bp = (const float4*)(g_state[t & 1]
                                   + (size_t)n * KCH * PLANE + (r0 + rr_f) * HW + w0_f);
                #pragma unroll
                for (int i = 0; i < KCH; i++) {
                    const float wv = WfS[i];
                    const float4 x0 = bp[i * (PLANE / 4)];
                    const float4 x1 = bp[i * (PLANE / 4) + 1];
                    a[0] += wv * x0.x; a[1] += wv * x0.y;
                    a[2] += wv * x0.z; a[3] += wv * x0.w;
                    a[4] += wv * x1.x; a[5] += wv * x1.y;
                    a[6] += wv * x1.z; a[7] += wv * x1.w;
                }
            }
            float* sp_ = &S[rr_f * HW + w0_f];
            *(float4*)sp_       = make_float4(a[0], a[1], a[2], a[3]);
            *(float4*)(sp_ + 4) = make_float4(a[4], a[5], a[6], a[7]);
        } else {
            // ======== partner halo rows (t>0) then H box sums ========
            if (t > 0) {
                if (tid2 < 224) {
                    const int jr = tid2 >> 4;
                    const int wq = (tid2 & 15) << 2;
                    const float4 v = *(const float4*)(g_state[t & 1] + plane_off
                                                      + (pg0 + jr) * HW + wq);
                    float* rp = &R_cur[(pj0 + jr) * RP + wq];
                    rp[0] = v.x; rp[1] = v.y; rp[2] = v.z; rp[3] = v.w;
                }
                asm volatile("bar.sync 1, 256;" ::: "memory");
            }
            // H: 480 row-segments on 256 threads (1st: all, 2nd: tid2<224)
            #pragma unroll
            for (int pass = 0; pass < 2; pass++) {
                const int item = tid2 + pass * 256;
                if (item < ROWS_L * 8) {
                    const int j = item >> 3;
                    const int s = (item & 7) << 3;
                    const float* row = &R_cur[j * RP];
                    float v[36];
                    #pragma unroll
                    for (int d = 0; d < 36; d++) {
                        const int w = s - 14 + d;
                        v[d] = (w >= 0 && w < HW) ? row[w] : 0.f;
                    }
                    float sa = 0.f, sc = 0.f;
                    #pragma unroll
                    for (int d = 0; d < 14; d++) { sa += v[d]; sc += v[d + 14]; }
                    float s29 = sa + sc + v[28];
                    H29[j * RP + s] = s29;
                    #pragma unroll
                    for (int p = 1; p < 8; p++) {
                        s29 += v[p + 28] - v[p - 1];
                        H29[j * RP + s + p] = s29;
                    }
                    float s9 = 0.f;
                    #pragma unroll
                    for (int d = 10; d < 19; d++) s9 += v[d];
                    H9[j * RP + s] = s9;
                    #pragma unroll
                    for (int p = 1; p < 8; p++) {
                        s9 += v[p + 18] - v[p + 9];
                        H9[j * RP + s + p] = s9;
                    }
                }
            }
        }
        __syncthreads();

        // ======== V: vertical sliding box sums + combine + update ========
        float xn_s[4];
        {
            float b29a = 0.f, b29b = 0.f, b9 = 0.f;
            #pragma unroll
            for (int d = 0; d < 14; d++) {
                b29a += H29[(rb + d) * RP + w_v];
                b29b += H29[(rb + 14 + d) * RP + w_v];
            }
            float b29 = b29a + b29b + H29[(rb + 28) * RP + w_v];
            #pragma unroll
            for (int d = 0; d < 9; d++) b9 += H9[(rb + 10 + d) * RP + w_v];

            float* dst = g_state[(t + 1) & 1];
            #pragma unroll
            for (int r = 0; r < 4; r++) {
                const int rr = rb + r;
                const int j  = rr + 14;
                if (r > 0) {
                    b29 += H29[(rr + 28) * RP + w_v] - H29[(rr - 1) * RP + w_v];
                    b9  += H9 [(j + 4)  * RP + w_v] - H9 [(j - 5)  * RP + w_v];
                }
                const float sp = inh * b29 + emin * b9 + bs_k;
                const float xo = R_cur[j * RP + w_v];
                const float xn = 0.8f * xo + 0.2f * fmaxf(S[rr * HW + w_v] + sp, 0.f);
                xn_s[r] = xn;
                R_nxt[j * RP + w_v] = xn;                       // interior rows for t+1
                dst[plane_off + (size_t)(r0 + rr) * HW + w_v] = xn;
            }
        }

        const size_t outb = ((size_t)(n * TSTEPS + t) * KCH + k) * PLANE;
        if (t < TSTEPS - 1) {
            __syncthreads();                   // all dst/R_nxt stores done, R/H/S reads done
            const unsigned target = gen0 + (unsigned)t + 1u;
            if (tid == 0) {
                __threadfence();
                if (atomicAdd(&g_bar_cnt, 1u) == NCTA - 1) {
                    g_bar_cnt = 0;
                    st_rel(&g_bar_gen, target);
                }
            }
            // out stores hidden behind other CTAs' arrivals
            #pragma unroll
            for (int r = 0; r < 4; r++)
                out[outb + (size_t)(r0 + rb + r) * HW + w_v] = xn_s[r];
            if (tid == 0) {
                while ((int)(ld_acq(&g_bar_gen) - target) < 0) { }
            }
            __syncthreads();
        } else {
            #pragma unroll
            for (int r = 0; r < 4; r++)
                out[outb + (size_t)(r0 + rb + r) * HW + w_v] = xn_s[r];
        }
    }
}

extern "C" void kernel_launch(void* const* d_in, const int* in_sizes, int n_in,
                              void* d_out, int out_size)
{
    const float* inbound = (const float*)d_in[0];
    const float* Wf      = (const float*)d_in[1];
    const float* bf      = (const float*)d_in[2];
    const float* Ws      = (const float*)d_in[3];
    const float* bs      = (const float*)d_in[4];
    float* out = (float*)d_out;

    const int smem_bytes = (4 * ROWS_L * RP + 32 * HW + KCH) * sizeof(float) + 16;
    static bool attr_set = false;
    if (!attr_set) {
        cudaFuncSetAttribute(persist_kernel,
                             cudaFuncAttributeMaxDynamicSharedMemorySize, smem_bytes);
        attr_set = true;
    }
    persist_kernel<<<NCTA, NTHR, smem_bytes>>>(inbound, Wf, bf, Ws, bs, out);
}